// round 10
// baseline (speedup 1.0000x reference)
#include <cuda_runtime.h>
#include <math.h>
#include <stdint.h>

#define Bq 2
#define Cc 1024
#define Tt 2048
#define Hh 16
#define CHd 64
#define Gg 32

// ---------------- scratch (device globals; no allocations) ----------------
__device__ float g_xn[(size_t)Bq * Cc * Tt];
__device__ float g_qkv[(size_t)Bq * 3 * Cc * Tt];
__device__ float g_a[(size_t)Bq * Cc * Tt];
__device__ float g_tab[Hh * (2 * Tt - 1)];
__device__ float g_part[128][2];

// ---------------- relative-position bias table ----------------
__global__ void fill_tab_kernel(const float* __restrict__ rel_emb) {
    int idx = blockIdx.x * 256 + threadIdx.x;
    const int NT = Hh * (2 * Tt - 1);
    if (idx >= NT) return;
    int h = idx / (2 * Tt - 1);
    int di = idx % (2 * Tt - 1);
    int n = di - (Tt - 1);            // n = q - k
    int ret = 0;
    if (n < 0) { ret = 16; n = -n; }
    int bucket;
    if (n < 8) {
        bucket = ret + n;
    } else {
        float v = logf((float)n * 0.125f) / logf(8.0f) * 8.0f;
        int vi = 8 + (int)v;
        if (vi > 15) vi = 15;
        bucket = ret + vi;
    }
    g_tab[h * (2 * Tt - 1) + di] = rel_emb[bucket * Hh + h] * 8.0f;
}

// ---------------- GroupNorm, two-pass ----------------
__global__ __launch_bounds__(256) void gn1_kernel(const float* __restrict__ x) {
    int blk = blockIdx.x;
    int b = blk >> 6, g = (blk >> 1) & 31, half = blk & 1;
    const float* xp = x + ((size_t)b * Cc + (size_t)g * 32) * Tt + half * 32768;
    int tid = threadIdx.x;
    float s = 0.f, s2 = 0.f;
    for (int i = tid * 4; i < 32768; i += 1024) {
        float4 v = *(const float4*)&xp[i];
        s += v.x + v.y + v.z + v.w;
        s2 = fmaf(v.x, v.x, fmaf(v.y, v.y, fmaf(v.z, v.z, fmaf(v.w, v.w, s2))));
    }
    for (int o = 16; o; o >>= 1) {
        s  += __shfl_xor_sync(0xffffffffu, s, o);
        s2 += __shfl_xor_sync(0xffffffffu, s2, o);
    }
    __shared__ float sh[2][8];
    int wid = tid >> 5, ln = tid & 31;
    if (ln == 0) { sh[0][wid] = s; sh[1][wid] = s2; }
    __syncthreads();
    if (tid == 0) {
        float a = 0.f, c = 0.f;
        for (int i = 0; i < 8; i++) { a += sh[0][i]; c += sh[1][i]; }
        g_part[blk][0] = a;
        g_part[blk][1] = c;
    }
}

__global__ __launch_bounds__(256) void gn2_kernel(const float* __restrict__ x,
                                                  const float* __restrict__ w,
                                                  const float* __restrict__ bb) {
    int blk = blockIdx.x;
    int b = blk >> 7, g = (blk >> 2) & 31, q = blk & 3;
    int pi = b * 64 + g * 2;
    float S  = g_part[pi][0] + g_part[pi + 1][0];
    float S2 = g_part[pi][1] + g_part[pi + 1][1];
    float mu = S / 65536.0f;
    float inv = rsqrtf(S2 / 65536.0f - mu * mu + 1e-5f);
    size_t base = ((size_t)b * Cc + (size_t)g * 32) * Tt + q * 16384;
    const float* xp = x + base;
    float* op = g_xn + base;
    int tid = threadIdx.x;
    for (int i = tid * 4; i < 16384; i += 1024) {
        int c = g * 32 + (q * 16384 + i) / 2048;
        float sw = w[c] * inv, sb = bb[c] - mu * sw;
        float4 v = *(const float4*)&xp[i];
        v.x = fmaf(v.x, sw, sb);
        v.y = fmaf(v.y, sw, sb);
        v.z = fmaf(v.z, sw, sb);
        v.w = fmaf(v.w, sw, sb);
        *(float4*)&op[i] = v;
    }
}

// MMA on raw fp32 operands: HW truncates to tf32 internally.
#define MMA_F(C, A0, A1, A2, A3, B0, B1) \
    asm volatile("mma.sync.aligned.m16n8k8.row.col.f32.tf32.tf32.f32 " \
                 "{%0,%1,%2,%3}, {%4,%5,%6,%7}, {%8,%9}, {%0,%1,%2,%3};" \
                 : "+f"((C)[0]), "+f"((C)[1]), "+f"((C)[2]), "+f"((C)[3]) \
                 : "r"(__float_as_uint(A0)), "r"(__float_as_uint(A1)), \
                   "r"(__float_as_uint(A2)), "r"(__float_as_uint(A3)), \
                   "r"(__float_as_uint(B0)), "r"(__float_as_uint(B1)))

__device__ __forceinline__ void cp16(uint32_t dst, const void* src) {
    asm volatile("cp.async.cg.shared.global [%0], [%1], 16;" :: "r"(dst), "l"(src));
}
#define CP_COMMIT() asm volatile("cp.async.commit_group;" ::: "memory")
#define CP_WAIT3()  asm volatile("cp.async.wait_group 3;" ::: "memory")
#define CP_WAIT1()  asm volatile("cp.async.wait_group 1;" ::: "memory")
#define CP_WAIT0()  asm volatile("cp.async.wait_group 0;" ::: "memory")

// ---------------- tf32 GEMM: cp.async 5-stage pipeline, BK=16 (R7/R9-proven) --------
#define GSTG 5
#define AW 20
#define BW 136
#define AST (128 * AW)
#define BST (16 * BW)
#define GEMM_SMEM (GSTG * (AST + BST) * 4)

template <bool PROJ>
__global__ __launch_bounds__(256, 2) void mma_gemm(const float* __restrict__ Wt,
                                                   const float* __restrict__ bias,
                                                   const float* __restrict__ resid,
                                                   float* __restrict__ outp) {
    const int N = Tt, K = Cc;
    int b = blockIdx.z;
    const float* Xb = (PROJ ? g_a : g_xn) + (size_t)b * Cc * Tt;
    float* Ob = PROJ ? (outp + (size_t)b * Cc * Tt) : (g_qkv + (size_t)b * 3 * Cc * Tt);
    const float* Rb = PROJ ? (resid + (size_t)b * Cc * Tt) : nullptr;

    extern __shared__ float gs[];
    float* As = gs;
    float* Bs = gs + GSTG * AST;
    uint32_t as_u = (uint32_t)__cvta_generic_to_shared(As);
    uint32_t bs_u = (uint32_t)__cvta_generic_to_shared(Bs);

    int m0 = blockIdx.y * 128, n0 = blockIdx.x * 128;
    int tid = threadIdx.x, lane = tid & 31, warp = tid >> 5;
    int wm = warp & 1, wn = warp >> 1;
    int g = lane >> 2, t = lane & 3;

    int arow = tid >> 2, akq = (tid & 3) * 4;
    int brow = tid >> 5, bnc = (tid & 31) * 4;
    const float* aSrc = Wt + (size_t)(m0 + arow) * K + akq;
    const float* bSrc = Xb + (size_t)brow * N + n0 + bnc;
    uint32_t aDst = as_u + (arow * AW + akq) * 4;
    uint32_t bDst = bs_u + (brow * BW + bnc) * 4;

    float acc[4][4][4];
#pragma unroll
    for (int i = 0; i < 4; i++)
#pragma unroll
        for (int j = 0; j < 4; j++)
#pragma unroll
            for (int q = 0; q < 4; q++) acc[i][j][q] = 0.f;

    const int NK = K / 16;

#define G_ISSUE(ST, KT) do { \
    cp16(aDst + (ST) * AST * 4, aSrc + (KT)); \
    cp16(aDst + ((ST) * AST + 64 * AW) * 4, aSrc + (size_t)64 * K + (KT)); \
    cp16(bDst + (ST) * BST * 4, bSrc + (size_t)(KT) * N); \
    cp16(bDst + ((ST) * BST + 8 * BW) * 4, bSrc + (size_t)(KT + 8) * N); \
} while (0)

#pragma unroll
    for (int s = 0; s < 4; s++) {
        G_ISSUE(s, s * 16);
        CP_COMMIT();
    }

    for (int i = 0; i < NK; i++) {
        int st = i % GSTG;
        CP_WAIT3();
        __syncthreads();
        if (i + 4 < NK) {
            int ns = (i + 4) % GSTG;
            G_ISSUE(ns, (i + 4) * 16);
        }
        CP_COMMIT();

        const float* A0 = As + st * AST + (size_t)wm * 64 * AW;
        const float* B0 = Bs + st * BST + wn * 32;
#pragma unroll
        for (int kk = 0; kk < 16; kk += 8) {
            float af[4][4];
            float bf[4][2];
#pragma unroll
            for (int mt = 0; mt < 4; mt++) {
                const float* ap = A0 + (mt * 16 + g) * AW + kk + t;
                af[mt][0] = ap[0];
                af[mt][1] = ap[8 * AW];
                af[mt][2] = ap[4];
                af[mt][3] = ap[8 * AW + 4];
            }
#pragma unroll
            for (int nt = 0; nt < 4; nt++) {
                const float* bp = B0 + (kk + t) * BW + nt * 8 + g;
                bf[nt][0] = bp[0];
                bf[nt][1] = bp[4 * BW];
            }
#pragma unroll
            for (int mt = 0; mt < 4; mt++)
#pragma unroll
                for (int nt = 0; nt < 4; nt++)
                    MMA_F(acc[mt][nt], af[mt][0], af[mt][1], af[mt][2], af[mt][3],
                          bf[nt][0], bf[nt][1]);
        }
    }
#undef G_ISSUE

    int gid = lane >> 2, tg = lane & 3;
#pragma unroll
    for (int tm = 0; tm < 4; tm++) {
        int rr = m0 + wm * 64 + tm * 16 + gid;
        float b0v = bias[rr], b1v = bias[rr + 8];
#pragma unroll
        for (int tn = 0; tn < 4; tn++) {
            int cc = n0 + wn * 32 + tn * 8 + tg * 2;
            size_t o0 = (size_t)rr * N + cc;
            size_t o1 = (size_t)(rr + 8) * N + cc;
            float2 v0 = make_float2(acc[tm][tn][0] + b0v, acc[tm][tn][1] + b0v);
            float2 v1 = make_float2(acc[tm][tn][2] + b1v, acc[tm][tn][3] + b1v);
            if (PROJ) {
                float2 r0 = *(const float2*)&Rb[o0];
                float2 r1 = *(const float2*)&Rb[o1];
                v0.x += r0.x; v0.y += r0.y;
                v1.x += r1.x; v1.y += r1.y;
            }
            *(float2*)&Ob[o0] = v0;
            *(float2*)&Ob[o1] = v1;
        }
    }
}

// ---------------- flash attention: Q=128, 4 warps x m=32, 3 CTAs/SM -----------------
// Single K + single V buffer, phase-split cp.async groups; 32-col softmax halves to
// cut registers; row-parity XOR swizzle on K/V staging for conflict-free V frags.
#define QW 136
#define KW 72
#define KTILE (64 * KW)
#define ATTN_SMEM ((64 * QW + 2 * KTILE) * 4)   // 71680 B -> 3 CTAs/SM
__global__ __launch_bounds__(128, 3) void attn_kernel() {
    extern __shared__ float sm[];
    float* Qs = sm;                  // [d 64][r 128 +pad]
    float* Ks = sm + 64 * QW;        // [d 64][c 64 +pad], row-parity swizzled
    float* Vs = Ks + KTILE;          // [d 64][c 64 +pad], row-parity swizzled
    uint32_t ks_u = (uint32_t)__cvta_generic_to_shared(Ks);
    uint32_t vs_u = (uint32_t)__cvta_generic_to_shared(Vs);

    int q0 = blockIdx.x * 128;
    int h = blockIdx.y;
    int b = blockIdx.z;
    int tid = threadIdx.x, L = tid & 31, w = tid >> 5;

    const float* qp = g_qkv + ((size_t)b * 3 * Cc + (size_t)h * 3 * CHd) * Tt;
    const float* kp = qp + (size_t)CHd * Tt;
    const float* vp = qp + (size_t)2 * CHd * Tt;

#define TILE_ISSUE(DSTU, SRC, K0) do { \
    _Pragma("unroll") \
    for (int ch = 0; ch < 8; ch++) { \
        int cid = ch * 128 + tid; \
        int d = cid >> 4, c4 = (cid & 15) * 4; \
        int cs = c4 ^ (((d >> 2) & 1) << 2); \
        cp16((DSTU) + (d * KW + cs) * 4, (SRC) + (size_t)d * Tt + (K0) + c4); \
    } \
} while (0)

    TILE_ISSUE(ks_u, kp, 0);
    CP_COMMIT();
    TILE_ISSUE(vs_u, vp, 0);
    CP_COMMIT();

    const float qsc = 0.125f;   // scale^2 = 1/sqrt(64)
    for (int idx = tid * 4; idx < 64 * 128; idx += 512) {
        int d = idx >> 7, r = idx & 127;
        float4 v = *(const float4*)&qp[(size_t)d * Tt + q0 + r];
        v.x *= qsc; v.y *= qsc; v.z *= qsc; v.w *= qsc;
        *(float4*)&Qs[d * QW + r] = v;
    }

    float o[2][8][4];
    float mx[2][2], lsum[2][2];
#pragma unroll
    for (int mt = 0; mt < 2; mt++) {
        mx[mt][0] = mx[mt][1] = -3.0e38f;
        lsum[mt][0] = lsum[mt][1] = 0.f;
#pragma unroll
        for (int i = 0; i < 8; i++)
#pragma unroll
            for (int j = 0; j < 4; j++) o[mt][i][j] = 0.f;
    }

    int g = L >> 2, t = L & 3;
    int cb = 2 * t;
    int sidx = (L & 28) | (t >> 1);
    int gx = g ^ 4;
    int sw = (g >> 2) << 2;      // 0 or 4: V-frag swizzle offsets
    int sw4 = sw ^ 4;

    const float* tb = g_tab + h * (2 * Tt - 1) + (Tt - 1) + q0 + 32 * w;

    float s[2][4][4];

    // one 32-column half: S -> softmax -> (caller interleaves loads) -> PV
#define S_HALF(HALF) do { \
    _Pragma("unroll") \
    for (int mt = 0; mt < 2; mt++) \
        _Pragma("unroll") \
        for (int nt = 0; nt < 4; nt++) \
            _Pragma("unroll") \
            for (int j = 0; j < 4; j++) s[mt][nt][j] = 0.f; \
    _Pragma("unroll") \
    for (int dt = 0; dt < 8; dt++) { \
        const float* q0p = &Qs[(8 * dt + t) * QW + 32 * w + g]; \
        float a00 = q0p[0],      a01 = q0p[8]; \
        float a02 = q0p[4 * QW], a03 = q0p[4 * QW + 8]; \
        float a10 = q0p[16],     a11 = q0p[24]; \
        float a12 = q0p[4 * QW + 16], a13 = q0p[4 * QW + 24]; \
        const float* kb0 = &Ks[(8 * dt + t) * KW + 32 * (HALF) + g]; \
        const float* kb1 = &Ks[(8 * dt + t + 4) * KW + 32 * (HALF) + gx]; \
        _Pragma("unroll") \
        for (int nt = 0; nt < 4; nt++) { \
            float b0 = kb0[8 * nt], b1 = kb1[8 * nt]; \
            MMA_F(s[0][nt], a00, a01, a02, a03, b0, b1); \
            MMA_F(s[1][nt], a10, a11, a12, a13, b0, b1); \
        } \
    } \
} while (0)

#define SOFTMAX_HALF(HALF, TBP) do { \
    _Pragma("unroll") \
    for (int mt = 0; mt < 2; mt++) { \
        const float* tq = (TBP) + 16 * mt; \
        float tm0 = -3.0e38f, tm1 = -3.0e38f; \
        _Pragma("unroll") \
        for (int nt = 0; nt < 4; nt++) { \
            int cc = 32 * (HALF) + 8 * nt + cb; \
            s[mt][nt][0] += tq[g - cc]; \
            s[mt][nt][1] += tq[g - cc - 1]; \
            s[mt][nt][2] += tq[g + 8 - cc]; \
            s[mt][nt][3] += tq[g + 8 - cc - 1]; \
            tm0 = fmaxf(tm0, fmaxf(s[mt][nt][0], s[mt][nt][1])); \
            tm1 = fmaxf(tm1, fmaxf(s[mt][nt][2], s[mt][nt][3])); \
        } \
        tm0 = fmaxf(tm0, __shfl_xor_sync(0xffffffffu, tm0, 1)); \
        tm0 = fmaxf(tm0, __shfl_xor_sync(0xffffffffu, tm0, 2)); \
        tm1 = fmaxf(tm1, __shfl_xor_sync(0xffffffffu, tm1, 1)); \
        tm1 = fmaxf(tm1, __shfl_xor_sync(0xffffffffu, tm1, 2)); \
        float mn0 = fmaxf(mx[mt][0], tm0), mn1 = fmaxf(mx[mt][1], tm1); \
        bool skip = __all_sync(0xffffffffu, \
                               (mn0 == mx[mt][0]) && (mn1 == mx[mt][1])); \
        float rs0 = 0.f, rs1 = 0.f; \
        _Pragma("unroll") \
        for (int nt = 0; nt < 4; nt++) { \
            s[mt][nt][0] = __expf(s[mt][nt][0] - mn0); \
            s[mt][nt][1] = __expf(s[mt][nt][1] - mn0); \
            s[mt][nt][2] = __expf(s[mt][nt][2] - mn1); \
            s[mt][nt][3] = __expf(s[mt][nt][3] - mn1); \
            rs0 += s[mt][nt][0] + s[mt][nt][1]; \
            rs1 += s[mt][nt][2] + s[mt][nt][3]; \
        } \
        rs0 += __shfl_xor_sync(0xffffffffu, rs0, 1); \
        rs0 += __shfl_xor_sync(0xffffffffu, rs0, 2); \
        rs1 += __shfl_xor_sync(0xffffffffu, rs1, 1); \
        rs1 += __shfl_xor_sync(0xffffffffu, rs1, 2); \
        if (skip) { \
            lsum[mt][0] += rs0; \
            lsum[mt][1] += rs1; \
        } else { \
            float sc0 = __expf(mx[mt][0] - mn0); \
            float sc1 = __expf(mx[mt][1] - mn1); \
            lsum[mt][0] = lsum[mt][0] * sc0 + rs0; \
            lsum[mt][1] = lsum[mt][1] * sc1 + rs1; \
            mx[mt][0] = mn0; mx[mt][1] = mn1; \
            _Pragma("unroll") \
            for (int nt = 0; nt < 8; nt++) { \
                o[mt][nt][0] *= sc0; o[mt][nt][1] *= sc0; \
                o[mt][nt][2] *= sc1; o[mt][nt][3] *= sc1; \
            } \
        } \
    } \
} while (0)

#define PV_HALF(HALF) do { \
    _Pragma("unroll") \
    for (int ct = 0; ct < 4; ct++) { \
        float pa[2][4]; \
        _Pragma("unroll") \
        for (int mt = 0; mt < 2; mt++) { \
            float v00 = __shfl_sync(0xffffffffu, s[mt][ct][0], sidx); \
            float v01 = __shfl_sync(0xffffffffu, s[mt][ct][1], sidx); \
            float v10 = __shfl_sync(0xffffffffu, s[mt][ct][2], sidx); \
            float v11 = __shfl_sync(0xffffffffu, s[mt][ct][3], sidx); \
            float w00 = __shfl_sync(0xffffffffu, s[mt][ct][0], sidx + 2); \
            float w01 = __shfl_sync(0xffffffffu, s[mt][ct][1], sidx + 2); \
            float w10 = __shfl_sync(0xffffffffu, s[mt][ct][2], sidx + 2); \
            float w11 = __shfl_sync(0xffffffffu, s[mt][ct][3], sidx + 2); \
            pa[mt][0] = (t & 1) ? v01 : v00; \
            pa[mt][1] = (t & 1) ? v11 : v10; \
            pa[mt][2] = (t & 1) ? w01 : w00; \
            pa[mt][3] = (t & 1) ? w11 : w10; \
        } \
        const float* vb = &Vs[g * KW + 32 * (HALF) + 8 * ct + t]; \
        _Pragma("unroll") \
        for (int nt = 0; nt < 8; nt++) { \
            float b0 = vb[8 * nt * KW + sw], b1 = vb[8 * nt * KW + sw4]; \
            MMA_F(o[0][nt], pa[0][0], pa[0][1], pa[0][2], pa[0][3], b0, b1); \
            MMA_F(o[1][nt], pa[1][0], pa[1][1], pa[1][2], pa[1][3], b0, b1); \
        } \
    } \
} while (0)

    const int NI = Tt / 64;
    for (int i = 0; i < NI; i++) {
        CP_WAIT1();                  // K(i) arrived (V(i) may be in flight)
        __syncthreads();
        const float* tbp = tb - i * 64;

        S_HALF(0);
        SOFTMAX_HALF(0, tbp);

        CP_WAIT0();                  // V(i) arrived
        __syncthreads();
        PV_HALF(0);

        S_HALF(1);
        __syncthreads();             // all warps done reading Ks
        if (i + 1 < NI) TILE_ISSUE(ks_u, kp, (i + 1) * 64);
        CP_COMMIT();

        SOFTMAX_HALF(1, tbp);
        PV_HALF(1);
        __syncthreads();             // all warps done reading Vs
        if (i + 1 < NI) TILE_ISSUE(vs_u, vp, (i + 1) * 64);
        CP_COMMIT();
    }
#undef TILE_ISSUE
#undef S_HALF
#undef SOFTMAX_HALF
#undef PV_HALF

    size_t hb = (size_t)b * Cc + (size_t)h * CHd;
#pragma unroll
    for (int mt = 0; mt < 2; mt++) {
        float il0 = 1.0f / lsum[mt][0], il1 = 1.0f / lsum[mt][1];
#pragma unroll
        for (int nt = 0; nt < 8; nt++) {
            int d = 8 * nt + cb;
            size_t base = (hb + d) * Tt + q0 + 32 * w + 16 * mt;
            g_a[base + g]          = o[mt][nt][0] * il0;
            g_a[base + Tt + g]     = o[mt][nt][1] * il0;
            g_a[base + g + 8]      = o[mt][nt][2] * il1;
            g_a[base + Tt + g + 8] = o[mt][nt][3] * il1;
        }
    }
}

// ---------------- launch ----------------
extern "C" void kernel_launch(void* const* d_in, const int* in_sizes, int n_in,
                              void* d_out, int out_size) {
    const float* x       = (const float*)d_in[0];
    const float* gn_w    = (const float*)d_in[1];
    const float* gn_b    = (const float*)d_in[2];
    const float* qkv_w   = (const float*)d_in[3];
    const float* qkv_b   = (const float*)d_in[4];
    const float* proj_w  = (const float*)d_in[5];
    const float* proj_b  = (const float*)d_in[6];
    const float* rel_emb = (const float*)d_in[7];
    float* out = (float*)d_out;
    (void)in_sizes; (void)n_in; (void)out_size;

    cudaFuncSetAttribute(mma_gemm<false>, cudaFuncAttributeMaxDynamicSharedMemorySize, GEMM_SMEM);
    cudaFuncSetAttribute(mma_gemm<true>,  cudaFuncAttributeMaxDynamicSharedMemorySize, GEMM_SMEM);
    cudaFuncSetAttribute(attn_kernel, cudaFuncAttributeMaxDynamicSharedMemorySize, ATTN_SMEM);

    fill_tab_kernel<<<(Hh * (2 * Tt - 1) + 255) / 256, 256>>>(rel_emb);
    gn1_kernel<<<128, 256>>>(x);
    gn2_kernel<<<256, 256>>>(x, gn_w, gn_b);
    mma_gemm<false><<<dim3(Tt / 128, (3 * Cc) / 128, Bq), 256, GEMM_SMEM>>>(qkv_w, qkv_b, nullptr, nullptr);
    attn_kernel<<<dim3(Tt / 128, Hh, Bq), 128, ATTN_SMEM>>>();
    mma_gemm<true><<<dim3(Tt / 128, Cc / 128, Bq), 256, GEMM_SMEM>>>(proj_w, proj_b, x, out);
}

// round 11
// speedup vs baseline: 1.0499x; 1.0499x over previous
#include <cuda_runtime.h>
#include <math.h>
#include <stdint.h>

#define Bq 2
#define Cc 1024
#define Tt 2048
#define Hh 16
#define CHd 64
#define Gg 32

// ---------------- scratch (device globals; no allocations) ----------------
__device__ float g_xn[(size_t)Bq * Cc * Tt];
__device__ float g_qkv[(size_t)Bq * 3 * Cc * Tt];
__device__ float g_a[(size_t)Bq * Cc * Tt];
__device__ float g_tab[Hh * (2 * Tt - 1)];
__device__ float g_part[128][2];

// ---------------- relative-position bias table ----------------
__global__ void fill_tab_kernel(const float* __restrict__ rel_emb) {
    int idx = blockIdx.x * 256 + threadIdx.x;
    const int NT = Hh * (2 * Tt - 1);
    if (idx >= NT) return;
    int h = idx / (2 * Tt - 1);
    int di = idx % (2 * Tt - 1);
    int n = di - (Tt - 1);            // n = q - k
    int ret = 0;
    if (n < 0) { ret = 16; n = -n; }
    int bucket;
    if (n < 8) {
        bucket = ret + n;
    } else {
        float v = logf((float)n * 0.125f) / logf(8.0f) * 8.0f;
        int vi = 8 + (int)v;
        if (vi > 15) vi = 15;
        bucket = ret + vi;
    }
    g_tab[h * (2 * Tt - 1) + di] = rel_emb[bucket * Hh + h] * 8.0f;
}

// ---------------- GroupNorm, two-pass ----------------
__global__ __launch_bounds__(256) void gn1_kernel(const float* __restrict__ x) {
    int blk = blockIdx.x;
    int b = blk >> 6, g = (blk >> 1) & 31, half = blk & 1;
    const float* xp = x + ((size_t)b * Cc + (size_t)g * 32) * Tt + half * 32768;
    int tid = threadIdx.x;
    float s = 0.f, s2 = 0.f;
    for (int i = tid * 4; i < 32768; i += 1024) {
        float4 v = *(const float4*)&xp[i];
        s += v.x + v.y + v.z + v.w;
        s2 = fmaf(v.x, v.x, fmaf(v.y, v.y, fmaf(v.z, v.z, fmaf(v.w, v.w, s2))));
    }
    for (int o = 16; o; o >>= 1) {
        s  += __shfl_xor_sync(0xffffffffu, s, o);
        s2 += __shfl_xor_sync(0xffffffffu, s2, o);
    }
    __shared__ float sh[2][8];
    int wid = tid >> 5, ln = tid & 31;
    if (ln == 0) { sh[0][wid] = s; sh[1][wid] = s2; }
    __syncthreads();
    if (tid == 0) {
        float a = 0.f, c = 0.f;
        for (int i = 0; i < 8; i++) { a += sh[0][i]; c += sh[1][i]; }
        g_part[blk][0] = a;
        g_part[blk][1] = c;
    }
}

__global__ __launch_bounds__(256) void gn2_kernel(const float* __restrict__ x,
                                                  const float* __restrict__ w,
                                                  const float* __restrict__ bb) {
    int blk = blockIdx.x;
    int b = blk >> 7, g = (blk >> 2) & 31, q = blk & 3;
    int pi = b * 64 + g * 2;
    float S  = g_part[pi][0] + g_part[pi + 1][0];
    float S2 = g_part[pi][1] + g_part[pi + 1][1];
    float mu = S / 65536.0f;
    float inv = rsqrtf(S2 / 65536.0f - mu * mu + 1e-5f);
    size_t base = ((size_t)b * Cc + (size_t)g * 32) * Tt + q * 16384;
    const float* xp = x + base;
    float* op = g_xn + base;
    int tid = threadIdx.x;
    for (int i = tid * 4; i < 16384; i += 1024) {
        int c = g * 32 + (q * 16384 + i) / 2048;
        float sw = w[c] * inv, sb = bb[c] - mu * sw;
        float4 v = *(const float4*)&xp[i];
        v.x = fmaf(v.x, sw, sb);
        v.y = fmaf(v.y, sw, sb);
        v.z = fmaf(v.z, sw, sb);
        v.w = fmaf(v.w, sw, sb);
        *(float4*)&op[i] = v;
    }
}

// MMA on raw fp32 operands: HW truncates to tf32 internally.
#define MMA_F(C, A0, A1, A2, A3, B0, B1) \
    asm volatile("mma.sync.aligned.m16n8k8.row.col.f32.tf32.tf32.f32 " \
                 "{%0,%1,%2,%3}, {%4,%5,%6,%7}, {%8,%9}, {%0,%1,%2,%3};" \
                 : "+f"((C)[0]), "+f"((C)[1]), "+f"((C)[2]), "+f"((C)[3]) \
                 : "r"(__float_as_uint(A0)), "r"(__float_as_uint(A1)), \
                   "r"(__float_as_uint(A2)), "r"(__float_as_uint(A3)), \
                   "r"(__float_as_uint(B0)), "r"(__float_as_uint(B1)))

__device__ __forceinline__ void cp16(uint32_t dst, const void* src) {
    asm volatile("cp.async.cg.shared.global [%0], [%1], 16;" :: "r"(dst), "l"(src));
}
#define CP_COMMIT() asm volatile("cp.async.commit_group;" ::: "memory")
#define CP_WAIT3()  asm volatile("cp.async.wait_group 3;" ::: "memory")
#define CP_WAIT1()  asm volatile("cp.async.wait_group 1;" ::: "memory")

// ---------------- tf32 GEMM: cp.async 5-stage pipeline, BK=16 (R7/R9-proven) --------
#define GSTG 5
#define AW 20
#define BW 136
#define AST (128 * AW)
#define BST (16 * BW)
#define GEMM_SMEM (GSTG * (AST + BST) * 4)

template <bool PROJ>
__global__ __launch_bounds__(256, 2) void mma_gemm(const float* __restrict__ Wt,
                                                   const float* __restrict__ bias,
                                                   const float* __restrict__ resid,
                                                   float* __restrict__ outp) {
    const int N = Tt, K = Cc;
    int b = blockIdx.z;
    const float* Xb = (PROJ ? g_a : g_xn) + (size_t)b * Cc * Tt;
    float* Ob = PROJ ? (outp + (size_t)b * Cc * Tt) : (g_qkv + (size_t)b * 3 * Cc * Tt);
    const float* Rb = PROJ ? (resid + (size_t)b * Cc * Tt) : nullptr;

    extern __shared__ float gs[];
    float* As = gs;
    float* Bs = gs + GSTG * AST;
    uint32_t as_u = (uint32_t)__cvta_generic_to_shared(As);
    uint32_t bs_u = (uint32_t)__cvta_generic_to_shared(Bs);

    int m0 = blockIdx.y * 128, n0 = blockIdx.x * 128;
    int tid = threadIdx.x, lane = tid & 31, warp = tid >> 5;
    int wm = warp & 1, wn = warp >> 1;
    int g = lane >> 2, t = lane & 3;

    int arow = tid >> 2, akq = (tid & 3) * 4;
    int brow = tid >> 5, bnc = (tid & 31) * 4;
    const float* aSrc = Wt + (size_t)(m0 + arow) * K + akq;
    const float* bSrc = Xb + (size_t)brow * N + n0 + bnc;
    uint32_t aDst = as_u + (arow * AW + akq) * 4;
    uint32_t bDst = bs_u + (brow * BW + bnc) * 4;

    float acc[4][4][4];
#pragma unroll
    for (int i = 0; i < 4; i++)
#pragma unroll
        for (int j = 0; j < 4; j++)
#pragma unroll
            for (int q = 0; q < 4; q++) acc[i][j][q] = 0.f;

    const int NK = K / 16;

#define G_ISSUE(ST, KT) do { \
    cp16(aDst + (ST) * AST * 4, aSrc + (KT)); \
    cp16(aDst + ((ST) * AST + 64 * AW) * 4, aSrc + (size_t)64 * K + (KT)); \
    cp16(bDst + (ST) * BST * 4, bSrc + (size_t)(KT) * N); \
    cp16(bDst + ((ST) * BST + 8 * BW) * 4, bSrc + (size_t)(KT + 8) * N); \
} while (0)

#pragma unroll
    for (int s = 0; s < 4; s++) {
        G_ISSUE(s, s * 16);
        CP_COMMIT();
    }

    for (int i = 0; i < NK; i++) {
        int st = i % GSTG;
        CP_WAIT3();
        __syncthreads();
        if (i + 4 < NK) {
            int ns = (i + 4) % GSTG;
            G_ISSUE(ns, (i + 4) * 16);
        }
        CP_COMMIT();

        const float* A0 = As + st * AST + (size_t)wm * 64 * AW;
        const float* B0 = Bs + st * BST + wn * 32;
#pragma unroll
        for (int kk = 0; kk < 16; kk += 8) {
            float af[4][4];
            float bf[4][2];
#pragma unroll
            for (int mt = 0; mt < 4; mt++) {
                const float* ap = A0 + (mt * 16 + g) * AW + kk + t;
                af[mt][0] = ap[0];
                af[mt][1] = ap[8 * AW];
                af[mt][2] = ap[4];
                af[mt][3] = ap[8 * AW + 4];
            }
#pragma unroll
            for (int nt = 0; nt < 4; nt++) {
                const float* bp = B0 + (kk + t) * BW + nt * 8 + g;
                bf[nt][0] = bp[0];
                bf[nt][1] = bp[4 * BW];
            }
#pragma unroll
            for (int mt = 0; mt < 4; mt++)
#pragma unroll
                for (int nt = 0; nt < 4; nt++)
                    MMA_F(acc[mt][nt], af[mt][0], af[mt][1], af[mt][2], af[mt][3],
                          bf[nt][0], bf[nt][1]);
        }
    }
#undef G_ISSUE

    int gid = lane >> 2, tg = lane & 3;
#pragma unroll
    for (int tm = 0; tm < 4; tm++) {
        int rr = m0 + wm * 64 + tm * 16 + gid;
        float b0v = bias[rr], b1v = bias[rr + 8];
#pragma unroll
        for (int tn = 0; tn < 4; tn++) {
            int cc = n0 + wn * 32 + tn * 8 + tg * 2;
            size_t o0 = (size_t)rr * N + cc;
            size_t o1 = (size_t)(rr + 8) * N + cc;
            float2 v0 = make_float2(acc[tm][tn][0] + b0v, acc[tm][tn][1] + b0v);
            float2 v1 = make_float2(acc[tm][tn][2] + b1v, acc[tm][tn][3] + b1v);
            if (PROJ) {
                float2 r0 = *(const float2*)&Rb[o0];
                float2 r1 = *(const float2*)&Rb[o1];
                v0.x += r0.x; v0.y += r0.y;
                v1.x += r1.x; v1.y += r1.y;
            }
            *(float2*)&Ob[o0] = v0;
            *(float2*)&Ob[o1] = v1;
        }
    }
}

// ---------------- flash attention: Q=128, 4 warps x m=32 (R9 structure) -------------
// K/V staging uses row-parity XOR swizzle (c4 ^= ((d>>2)&1)<<2) so the V B-frag
// loads are bank-conflict-free; K/Q reads compensated (g^4 on upper K row, sw on V).
#define QW 136
#define KW 72
#define KVST (64 * KW)
#define ATTN_SMEM ((64 * QW + 4 * KVST) * 4) // 106496 B
__global__ __launch_bounds__(128, 2) void attn_kernel() {
    extern __shared__ float sm[];
    float* Qs = sm;                          // [d][r]
    float* KV = sm + 64 * QW;                // [stage][{K,V}][d][c]
    uint32_t kv_u = (uint32_t)__cvta_generic_to_shared(KV);

    int q0 = blockIdx.x * 128;
    int h = blockIdx.y;
    int b = blockIdx.z;
    int tid = threadIdx.x, L = tid & 31, w = tid >> 5;

    const float* qp = g_qkv + ((size_t)b * 3 * Cc + (size_t)h * 3 * CHd) * Tt;
    const float* kp = qp + (size_t)CHd * Tt;
    const float* vp = qp + (size_t)2 * CHd * Tt;

#define KV_ISSUE(ST, K0) do { \
    _Pragma("unroll") \
    for (int ch = 0; ch < 8; ch++) { \
        int cid = ch * 128 + tid; \
        int d = cid >> 4, c4 = (cid & 15) * 4; \
        int cs = c4 ^ (((d >> 2) & 1) << 2); \
        cp16(kv_u + ((ST) * 2 * KVST + d * KW + cs) * 4, kp + (size_t)d * Tt + (K0) + c4); \
        cp16(kv_u + (((ST) * 2 + 1) * KVST + d * KW + cs) * 4, vp + (size_t)d * Tt + (K0) + c4); \
    } \
} while (0)

    KV_ISSUE(0, 0);
    CP_COMMIT();

    const float qsc = 0.125f;   // scale^2 = 1/sqrt(64)
    for (int idx = tid * 4; idx < 64 * 128; idx += 512) {
        int d = idx >> 7, r = idx & 127;
        float4 v = *(const float4*)&qp[(size_t)d * Tt + q0 + r];
        v.x *= qsc; v.y *= qsc; v.z *= qsc; v.w *= qsc;
        *(float4*)&Qs[d * QW + r] = v;
    }

    float o[2][8][4];
    float mx[2][2], lsum[2][2];
#pragma unroll
    for (int mt = 0; mt < 2; mt++) {
        mx[mt][0] = mx[mt][1] = -3.0e38f;
        lsum[mt][0] = lsum[mt][1] = 0.f;
#pragma unroll
        for (int i = 0; i < 8; i++)
#pragma unroll
            for (int j = 0; j < 4; j++) o[mt][i][j] = 0.f;
    }

    int g = L >> 2, t = L & 3;
    int cb = 2 * t;
    int sidx = (L & 28) | (t >> 1);
    int gx = g ^ 4;                 // K upper-row swizzle compensation
    int sw = (g >> 2) << 2;         // V row-parity swizzle offsets
    int sw4 = sw ^ 4;

    const float* tb = g_tab + h * (2 * Tt - 1) + (Tt - 1) + q0 + 32 * w;

    const int NI = Tt / 64;
    for (int i = 0; i < NI; i++) {
        int st = i & 1;
        if (i > 0) __syncthreads();
        if (i + 1 < NI) KV_ISSUE(st ^ 1, (i + 1) * 64);
        CP_COMMIT();
        CP_WAIT1();
        __syncthreads();

        const float* Ks = KV + st * 2 * KVST;
        const float* Vs = Ks + KVST;

        // ---- S = Q K^T ----
        float s[2][8][4];
#pragma unroll
        for (int mt = 0; mt < 2; mt++)
#pragma unroll
            for (int nt = 0; nt < 8; nt++)
#pragma unroll
                for (int j = 0; j < 4; j++) s[mt][nt][j] = 0.f;
#pragma unroll
        for (int dt = 0; dt < 8; dt++) {
            const float* q0p = &Qs[(8 * dt + t) * QW + 32 * w + g];
            float a[2][4];
#pragma unroll
            for (int mt = 0; mt < 2; mt++) {
                a[mt][0] = q0p[16 * mt];
                a[mt][1] = q0p[16 * mt + 8];
                a[mt][2] = q0p[4 * QW + 16 * mt];
                a[mt][3] = q0p[4 * QW + 16 * mt + 8];
            }
            const float* kb0 = &Ks[(8 * dt + t) * KW + g];        // row parity 0
            const float* kb1 = &Ks[(8 * dt + t + 4) * KW + gx];   // row parity 1
#pragma unroll
            for (int nt = 0; nt < 8; nt++) {
                float b0 = kb0[8 * nt], b1 = kb1[8 * nt];
                MMA_F(s[0][nt], a[0][0], a[0][1], a[0][2], a[0][3], b0, b1);
                MMA_F(s[1][nt], a[1][0], a[1][1], a[1][2], a[1][3], b0, b1);
            }
        }

        // ---- bias + online softmax per m-tile (vote-skip rescale) ----
        const float* tbp = tb - i * 64;
#pragma unroll
        for (int mt = 0; mt < 2; mt++) {
            const float* tq = tbp + 16 * mt;
            float tm0 = -3.0e38f, tm1 = -3.0e38f;
#pragma unroll
            for (int nt = 0; nt < 8; nt++) {
                int cc = 8 * nt + cb;
                s[mt][nt][0] += tq[g - cc];
                s[mt][nt][1] += tq[g - cc - 1];
                s[mt][nt][2] += tq[g + 8 - cc];
                s[mt][nt][3] += tq[g + 8 - cc - 1];
                tm0 = fmaxf(tm0, fmaxf(s[mt][nt][0], s[mt][nt][1]));
                tm1 = fmaxf(tm1, fmaxf(s[mt][nt][2], s[mt][nt][3]));
            }
            tm0 = fmaxf(tm0, __shfl_xor_sync(0xffffffffu, tm0, 1));
            tm0 = fmaxf(tm0, __shfl_xor_sync(0xffffffffu, tm0, 2));
            tm1 = fmaxf(tm1, __shfl_xor_sync(0xffffffffu, tm1, 1));
            tm1 = fmaxf(tm1, __shfl_xor_sync(0xffffffffu, tm1, 2));
            float mn0 = fmaxf(mx[mt][0], tm0), mn1 = fmaxf(mx[mt][1], tm1);
            bool skip = __all_sync(0xffffffffu,
                                   (mn0 == mx[mt][0]) && (mn1 == mx[mt][1]));
            float rs0 = 0.f, rs1 = 0.f;
#pragma unroll
            for (int nt = 0; nt < 8; nt++) {
                s[mt][nt][0] = __expf(s[mt][nt][0] - mn0);
                s[mt][nt][1] = __expf(s[mt][nt][1] - mn0);
                s[mt][nt][2] = __expf(s[mt][nt][2] - mn1);
                s[mt][nt][3] = __expf(s[mt][nt][3] - mn1);
                rs0 += s[mt][nt][0] + s[mt][nt][1];
                rs1 += s[mt][nt][2] + s[mt][nt][3];
            }
            rs0 += __shfl_xor_sync(0xffffffffu, rs0, 1);
            rs0 += __shfl_xor_sync(0xffffffffu, rs0, 2);
            rs1 += __shfl_xor_sync(0xffffffffu, rs1, 1);
            rs1 += __shfl_xor_sync(0xffffffffu, rs1, 2);
            if (skip) {
                lsum[mt][0] += rs0;
                lsum[mt][1] += rs1;
            } else {
                float sc0 = __expf(mx[mt][0] - mn0);
                float sc1 = __expf(mx[mt][1] - mn1);
                lsum[mt][0] = lsum[mt][0] * sc0 + rs0;
                lsum[mt][1] = lsum[mt][1] * sc1 + rs1;
                mx[mt][0] = mn0; mx[mt][1] = mn1;
#pragma unroll
                for (int nt = 0; nt < 8; nt++) {
                    o[mt][nt][0] *= sc0; o[mt][nt][1] *= sc0;
                    o[mt][nt][2] *= sc1; o[mt][nt][3] *= sc1;
                }
            }
        }

        // ---- O += P V  (V-frag reused across 2 m-tiles; P via shuffles) ----
#pragma unroll
        for (int ct = 0; ct < 8; ct++) {
            float pa[2][4];
#pragma unroll
            for (int mt = 0; mt < 2; mt++) {
                float v00 = __shfl_sync(0xffffffffu, s[mt][ct][0], sidx);
                float v01 = __shfl_sync(0xffffffffu, s[mt][ct][1], sidx);
                float v10 = __shfl_sync(0xffffffffu, s[mt][ct][2], sidx);
                float v11 = __shfl_sync(0xffffffffu, s[mt][ct][3], sidx);
                float w00 = __shfl_sync(0xffffffffu, s[mt][ct][0], sidx + 2);
                float w01 = __shfl_sync(0xffffffffu, s[mt][ct][1], sidx + 2);
                float w10 = __shfl_sync(0xffffffffu, s[mt][ct][2], sidx + 2);
                float w11 = __shfl_sync(0xffffffffu, s[mt][ct][3], sidx + 2);
                pa[mt][0] = (t & 1) ? v01 : v00;
                pa[mt][1] = (t & 1) ? v11 : v10;
                pa[mt][2] = (t & 1) ? w01 : w00;
                pa[mt][3] = (t & 1) ? w11 : w10;
            }
            const float* vb = &Vs[g * KW + 8 * ct + t];
#pragma unroll
            for (int nt = 0; nt < 8; nt++) {
                float b0 = vb[8 * nt * KW + sw], b1 = vb[8 * nt * KW + sw4];
                MMA_F(o[0][nt], pa[0][0], pa[0][1], pa[0][2], pa[0][3], b0, b1);
                MMA_F(o[1][nt], pa[1][0], pa[1][1], pa[1][2], pa[1][3], b0, b1);
            }
        }
    }
#undef KV_ISSUE

    size_t hb = (size_t)b * Cc + (size_t)h * CHd;
#pragma unroll
    for (int mt = 0; mt < 2; mt++) {
        float il0 = 1.0f / lsum[mt][0], il1 = 1.0f / lsum[mt][1];
#pragma unroll
        for (int nt = 0; nt < 8; nt++) {
            int d = 8 * nt + cb;
            size_t base = (hb + d) * Tt + q0 + 32 * w + 16 * mt;
            g_a[base + g]          = o[mt][nt][0] * il0;
            g_a[base + Tt + g]     = o[mt][nt][1] * il0;
            g_a[base + g + 8]      = o[mt][nt][2] * il1;
            g_a[base + Tt + g + 8] = o[mt][nt][3] * il1;
        }
    }
}

// ---------------- launch ----------------
extern "C" void kernel_launch(void* const* d_in, const int* in_sizes, int n_in,
                              void* d_out, int out_size) {
    const float* x       = (const float*)d_in[0];
    const float* gn_w    = (const float*)d_in[1];
    const float* gn_b    = (const float*)d_in[2];
    const float* qkv_w   = (const float*)d_in[3];
    const float* qkv_b   = (const float*)d_in[4];
    const float* proj_w  = (const float*)d_in[5];
    const float* proj_b  = (const float*)d_in[6];
    const float* rel_emb = (const float*)d_in[7];
    float* out = (float*)d_out;
    (void)in_sizes; (void)n_in; (void)out_size;

    cudaFuncSetAttribute(mma_gemm<false>, cudaFuncAttributeMaxDynamicSharedMemorySize, GEMM_SMEM);
    cudaFuncSetAttribute(mma_gemm<true>,  cudaFuncAttributeMaxDynamicSharedMemorySize, GEMM_SMEM);
    cudaFuncSetAttribute(attn_kernel, cudaFuncAttributeMaxDynamicSharedMemorySize, ATTN_SMEM);

    fill_tab_kernel<<<(Hh * (2 * Tt - 1) + 255) / 256, 256>>>(rel_emb);
    gn1_kernel<<<128, 256>>>(x);
    gn2_kernel<<<256, 256>>>(x, gn_w, gn_b);
    mma_gemm<false><<<dim3(Tt / 128, (3 * Cc) / 128, Bq), 256, GEMM_SMEM>>>(qkv_w, qkv_b, nullptr, nullptr);
    attn_kernel<<<dim3(Tt / 128, Hh, Bq), 128, ATTN_SMEM>>>();
    mma_gemm<true><<<dim3(Tt / 128, Cc / 128, Bq), 256, GEMM_SMEM>>>(proj_w, proj_b, x, out);
}

// round 13
// speedup vs baseline: 1.4034x; 1.3368x over previous
#include <cuda_runtime.h>
#include <cuda_fp16.h>
#include <math.h>
#include <stdint.h>

#define Bq 2
#define Cc 1024
#define Tt 2048
#define Hh 16
#define CHd 64
#define Gg 32

// ---------------- scratch (device globals; no allocations) ----------------
__device__ __half g_xn_h[(size_t)Bq * Cc * Tt];      // GroupNorm output (half)
__device__ float  g_qkv[(size_t)Bq * 3 * Cc * Tt];   // QKV output (fp32, attn input)
__device__ __half g_a_h[(size_t)Bq * Cc * Tt];       // attention output (half)
__device__ __half g_wq_h[(size_t)3 * Cc * Cc];       // qkv_w in half
__device__ __half g_wp_h[(size_t)Cc * Cc];           // proj_w in half
__device__ float  g_tab[Hh * (2 * Tt - 1)];
__device__ float  g_part[128][2];

// ---------------- fp32 -> fp16 weight conversion ----------------
__global__ void f2h_kernel(const float* __restrict__ s, __half* __restrict__ d, int n) {
    int i = (blockIdx.x * 256 + threadIdx.x) * 8;
    if (i >= n) return;
    float4 a = *(const float4*)&s[i];
    float4 b = *(const float4*)&s[i + 4];
    __half2 h[4] = {__floats2half2_rn(a.x, a.y), __floats2half2_rn(a.z, a.w),
                    __floats2half2_rn(b.x, b.y), __floats2half2_rn(b.z, b.w)};
    *(uint4*)&d[i] = *(uint4*)h;
}

// ---------------- relative-position bias table ----------------
__global__ void fill_tab_kernel(const float* __restrict__ rel_emb) {
    int idx = blockIdx.x * 256 + threadIdx.x;
    const int NT = Hh * (2 * Tt - 1);
    if (idx >= NT) return;
    int h = idx / (2 * Tt - 1);
    int di = idx % (2 * Tt - 1);
    int n = di - (Tt - 1);            // n = q - k
    int ret = 0;
    if (n < 0) { ret = 16; n = -n; }
    int bucket;
    if (n < 8) {
        bucket = ret + n;
    } else {
        float v = logf((float)n * 0.125f) / logf(8.0f) * 8.0f;
        int vi = 8 + (int)v;
        if (vi > 15) vi = 15;
        bucket = ret + vi;
    }
    g_tab[h * (2 * Tt - 1) + di] = rel_emb[bucket * Hh + h] * 8.0f;
}

// ---------------- GroupNorm, two-pass ----------------
__global__ __launch_bounds__(256) void gn1_kernel(const float* __restrict__ x) {
    int blk = blockIdx.x;
    int b = blk >> 6, g = (blk >> 1) & 31, half = blk & 1;
    const float* xp = x + ((size_t)b * Cc + (size_t)g * 32) * Tt + half * 32768;
    int tid = threadIdx.x;
    float s = 0.f, s2 = 0.f;
    for (int i = tid * 4; i < 32768; i += 1024) {
        float4 v = *(const float4*)&xp[i];
        s += v.x + v.y + v.z + v.w;
        s2 = fmaf(v.x, v.x, fmaf(v.y, v.y, fmaf(v.z, v.z, fmaf(v.w, v.w, s2))));
    }
    for (int o = 16; o; o >>= 1) {
        s  += __shfl_xor_sync(0xffffffffu, s, o);
        s2 += __shfl_xor_sync(0xffffffffu, s2, o);
    }
    __shared__ float sh[2][8];
    int wid = tid >> 5, ln = tid & 31;
    if (ln == 0) { sh[0][wid] = s; sh[1][wid] = s2; }
    __syncthreads();
    if (tid == 0) {
        float a = 0.f, c = 0.f;
        for (int i = 0; i < 8; i++) { a += sh[0][i]; c += sh[1][i]; }
        g_part[blk][0] = a;
        g_part[blk][1] = c;
    }
}

__global__ __launch_bounds__(256) void gn2_kernel(const float* __restrict__ x,
                                                  const float* __restrict__ w,
                                                  const float* __restrict__ bb) {
    int blk = blockIdx.x;
    int b = blk >> 7, g = (blk >> 2) & 31, q = blk & 3;
    int pi = b * 64 + g * 2;
    float S  = g_part[pi][0] + g_part[pi + 1][0];
    float S2 = g_part[pi][1] + g_part[pi + 1][1];
    float mu = S / 65536.0f;
    float inv = rsqrtf(S2 / 65536.0f - mu * mu + 1e-5f);
    size_t base = ((size_t)b * Cc + (size_t)g * 32) * Tt + q * 16384;
    const float* xp = x + base;
    __half* op = g_xn_h + base;
    int tid = threadIdx.x;
    for (int i = tid * 4; i < 16384; i += 1024) {
        int c = g * 32 + (q * 16384 + i) / 2048;
        float sw = w[c] * inv, sb = bb[c] - mu * sw;
        float4 v = *(const float4*)&xp[i];
        __half2 h0 = __floats2half2_rn(fmaf(v.x, sw, sb), fmaf(v.y, sw, sb));
        __half2 h1 = __floats2half2_rn(fmaf(v.z, sw, sb), fmaf(v.w, sw, sb));
        *(uint2*)&op[i] = make_uint2(*(uint32_t*)&h0, *(uint32_t*)&h1);
    }
}

// ---------------- shared PTX helpers ----------------
// tf32 mma on raw fp32 (attention, unchanged)
#define MMA_F(C, A0, A1, A2, A3, B0, B1) \
    asm volatile("mma.sync.aligned.m16n8k8.row.col.f32.tf32.tf32.f32 " \
                 "{%0,%1,%2,%3}, {%4,%5,%6,%7}, {%8,%9}, {%0,%1,%2,%3};" \
                 : "+f"((C)[0]), "+f"((C)[1]), "+f"((C)[2]), "+f"((C)[3]) \
                 : "r"(__float_as_uint(A0)), "r"(__float_as_uint(A1)), \
                   "r"(__float_as_uint(A2)), "r"(__float_as_uint(A3)), \
                   "r"(__float_as_uint(B0)), "r"(__float_as_uint(B1)))

// fp16 mma (GEMMs)
#define MMA_H(C, A0, A1, A2, A3, B0, B1) \
    asm volatile("mma.sync.aligned.m16n8k16.row.col.f32.f16.f16.f32 " \
                 "{%0,%1,%2,%3}, {%4,%5,%6,%7}, {%8,%9}, {%0,%1,%2,%3};" \
                 : "+f"((C)[0]), "+f"((C)[1]), "+f"((C)[2]), "+f"((C)[3]) \
                 : "r"(A0), "r"(A1), "r"(A2), "r"(A3), "r"(B0), "r"(B1))

#define LDSM4(R0, R1, R2, R3, ADDR) \
    asm volatile("ldmatrix.sync.aligned.m8n8.x4.shared.b16 {%0,%1,%2,%3}, [%4];" \
                 : "=r"(R0), "=r"(R1), "=r"(R2), "=r"(R3) : "r"(ADDR))

#define LDSM2T(R0, R1, ADDR) \
    asm volatile("ldmatrix.sync.aligned.m8n8.x2.trans.shared.b16 {%0,%1}, [%2];" \
                 : "=r"(R0), "=r"(R1) : "r"(ADDR))

__device__ __forceinline__ void cp16(uint32_t dst, const void* src) {
    asm volatile("cp.async.cg.shared.global [%0], [%1], 16;" :: "r"(dst), "l"(src));
}
#define CP_COMMIT() asm volatile("cp.async.commit_group;" ::: "memory")
#define CP_WAIT3()  asm volatile("cp.async.wait_group 3;" ::: "memory")
#define CP_WAIT1()  asm volatile("cp.async.wait_group 1;" ::: "memory")

// ---------------- fp16 GEMM: cp.async 5-stage pipeline, BK=16, ldmatrix frags -------
// Out[m][n] = sum_k W[m][k] X[k][n] + bias[m] (+resid).
// A stage: 128 rows x 16 halfs (32B), chunk-swizzled. B stage: 16 k x 128 n halfs.
#define HAST 4096
#define HBST 4096
#define HSTG 5
#define HGEMM_SMEM (HSTG * (HAST + HBST))   // 40960 B

template <bool PROJ>
__global__ __launch_bounds__(256, 2) void hgemm(const __half* __restrict__ Wh,
                                                const float* __restrict__ bias,
                                                const float* __restrict__ resid,
                                                float* __restrict__ outp) {
    const int N = Tt, K = Cc;
    int b = blockIdx.z;
    const __half* Xh = (PROJ ? g_a_h : g_xn_h) + (size_t)b * Cc * Tt;
    float* Ob = PROJ ? (outp + (size_t)b * Cc * Tt) : (g_qkv + (size_t)b * 3 * Cc * Tt);
    const float* Rb = PROJ ? (resid + (size_t)b * Cc * Tt) : nullptr;

    extern __shared__ __align__(128) char hs[];
    uint32_t a_u = (uint32_t)__cvta_generic_to_shared(hs);
    uint32_t b_u = a_u + HSTG * HAST;

    int m0 = blockIdx.y * 128, n0 = blockIdx.x * 128;
    int tid = threadIdx.x, lane = tid & 31, warp = tid >> 5;
    int wm = warp & 1, wn = warp >> 1;

    // staging coords
    int arow = tid >> 1, ac = tid & 1;                    // A: 128 rows x 2 chunks
    int brow = tid >> 4, bc = tid & 15;                   // B: 16 k-rows x 16 chunks
    const __half* aSrc = Wh + (size_t)(m0 + arow) * K + ac * 8;
    const __half* bSrc = Xh + (size_t)brow * N + n0 + bc * 8;
    uint32_t aDst = a_u + ((arow * 2 + (ac ^ ((arow >> 2) & 1))) << 4);
    uint32_t bDst = b_u + ((brow * 16 + (bc ^ (brow & 7))) << 4);

    // ldmatrix addresses (offsets within one stage)
    int l15 = lane & 15, lc = lane >> 4;
    uint32_t aAddr[4], bAddr[4];
#pragma unroll
    for (int mt = 0; mt < 4; mt++) {
        int row = wm * 64 + mt * 16 + l15;
        aAddr[mt] = a_u + ((row * 2 + (lc ^ ((row >> 2) & 1))) << 4);
    }
#pragma unroll
    for (int nt = 0; nt < 4; nt++) {
        int c = wn * 4 + nt;
        bAddr[nt] = b_u + ((l15 * 16 + (c ^ (l15 & 7))) << 4);
    }

    float acc[4][4][4];
#pragma unroll
    for (int i = 0; i < 4; i++)
#pragma unroll
        for (int j = 0; j < 4; j++)
#pragma unroll
            for (int q = 0; q < 4; q++) acc[i][j][q] = 0.f;

    const int NK = K / 16;   // 64

#define HG_ISSUE(ST, KT) do { \
    cp16(aDst + (ST) * HAST, aSrc + (KT)); \
    cp16(bDst + (ST) * HBST, bSrc + (size_t)(KT) * N); \
} while (0)

#pragma unroll
    for (int s = 0; s < 4; s++) {
        HG_ISSUE(s, s * 16);
        CP_COMMIT();
    }

    for (int i = 0; i < NK; i++) {
        int st = i % HSTG;
        CP_WAIT3();
        __syncthreads();
        if (i + 4 < NK) {
            int ns = (i + 4) % HSTG;
            HG_ISSUE(ns, (i + 4) * 16);
        }
        CP_COMMIT();

        uint32_t af[4][4], bf[4][2];
#pragma unroll
        for (int mt = 0; mt < 4; mt++)
            LDSM4(af[mt][0], af[mt][1], af[mt][2], af[mt][3], aAddr[mt] + st * HAST);
#pragma unroll
        for (int nt = 0; nt < 4; nt++)
            LDSM2T(bf[nt][0], bf[nt][1], bAddr[nt] + st * HBST);
#pragma unroll
        for (int mt = 0; mt < 4; mt++)
#pragma unroll
            for (int nt = 0; nt < 4; nt++)
                MMA_H(acc[mt][nt], af[mt][0], af[mt][1], af[mt][2], af[mt][3],
                      bf[nt][0], bf[nt][1]);
    }
#undef HG_ISSUE

    int gid = lane >> 2, tg = lane & 3;
#pragma unroll
    for (int tm = 0; tm < 4; tm++) {
        int rr = m0 + wm * 64 + tm * 16 + gid;
        float b0v = bias[rr], b1v = bias[rr + 8];
#pragma unroll
        for (int tn = 0; tn < 4; tn++) {
            int cc = n0 + wn * 32 + tn * 8 + tg * 2;
            size_t o0 = (size_t)rr * N + cc;
            size_t o1 = (size_t)(rr + 8) * N + cc;
            float2 v0 = make_float2(acc[tm][tn][0] + b0v, acc[tm][tn][1] + b0v);
            float2 v1 = make_float2(acc[tm][tn][2] + b1v, acc[tm][tn][3] + b1v);
            if (PROJ) {
                float2 r0 = *(const float2*)&Rb[o0];
                float2 r1 = *(const float2*)&Rb[o1];
                v0.x += r0.x; v0.y += r0.y;
                v1.x += r1.x; v1.y += r1.y;
            }
            *(float2*)&Ob[o0] = v0;
            *(float2*)&Ob[o1] = v1;
        }
    }
}

// ---------------- flash attention: Q=128, 4 warps x m=32 (R11 best) -----------------
// Identical to the 544.8us config except the epilogue stores half into g_a_h.
#define QW 136
#define KW 72
#define KVST (64 * KW)
#define ATTN_SMEM ((64 * QW + 4 * KVST) * 4) // 106496 B
__global__ __launch_bounds__(128, 2) void attn_kernel() {
    extern __shared__ float sm[];
    float* Qs = sm;
    float* KV = sm + 64 * QW;
    uint32_t kv_u = (uint32_t)__cvta_generic_to_shared(KV);

    int q0 = blockIdx.x * 128;
    int h = blockIdx.y;
    int b = blockIdx.z;
    int tid = threadIdx.x, L = tid & 31, w = tid >> 5;

    const float* qp = g_qkv + ((size_t)b * 3 * Cc + (size_t)h * 3 * CHd) * Tt;
    const float* kp = qp + (size_t)CHd * Tt;
    const float* vp = qp + (size_t)2 * CHd * Tt;

#define KV_ISSUE(ST, K0) do { \
    _Pragma("unroll") \
    for (int ch = 0; ch < 8; ch++) { \
        int cid = ch * 128 + tid; \
        int d = cid >> 4, c4 = (cid & 15) * 4; \
        int cs = c4 ^ (((d >> 2) & 1) << 2); \
        cp16(kv_u + ((ST) * 2 * KVST + d * KW + cs) * 4, kp + (size_t)d * Tt + (K0) + c4); \
        cp16(kv_u + (((ST) * 2 + 1) * KVST + d * KW + cs) * 4, vp + (size_t)d * Tt + (K0) + c4); \
    } \
} while (0)

    KV_ISSUE(0, 0);
    CP_COMMIT();

    const float qsc = 0.125f;
    for (int idx = tid * 4; idx < 64 * 128; idx += 512) {
        int d = idx >> 7, r = idx & 127;
        float4 v = *(const float4*)&qp[(size_t)d * Tt + q0 + r];
        v.x *= qsc; v.y *= qsc; v.z *= qsc; v.w *= qsc;
        *(float4*)&Qs[d * QW + r] = v;
    }

    float o[2][8][4];
    float mx[2][2], lsum[2][2];
#pragma unroll
    for (int mt = 0; mt < 2; mt++) {
        mx[mt][0] = mx[mt][1] = -3.0e38f;
        lsum[mt][0] = lsum[mt][1] = 0.f;
#pragma unroll
        for (int i = 0; i < 8; i++)
#pragma unroll
            for (int j = 0; j < 4; j++) o[mt][i][j] = 0.f;
    }

    int g = L >> 2, t = L & 3;
    int cb = 2 * t;
    int sidx = (L & 28) | (t >> 1);
    int gx = g ^ 4;
    int sw = (g >> 2) << 2;
    int sw4 = sw ^ 4;

    const float* tb = g_tab + h * (2 * Tt - 1) + (Tt - 1) + q0 + 32 * w;

    const int NI = Tt / 64;
    for (int i = 0; i < NI; i++) {
        int st = i & 1;
        if (i > 0) __syncthreads();
        if (i + 1 < NI) KV_ISSUE(st ^ 1, (i + 1) * 64);
        CP_COMMIT();
        CP_WAIT1();
        __syncthreads();

        const float* Ks = KV + st * 2 * KVST;
        const float* Vs = Ks + KVST;

        float s[2][8][4];
#pragma unroll
        for (int mt = 0; mt < 2; mt++)
#pragma unroll
            for (int nt = 0; nt < 8; nt++)
#pragma unroll
                for (int j = 0; j < 4; j++) s[mt][nt][j] = 0.f;
#pragma unroll
        for (int dt = 0; dt < 8; dt++) {
            const float* q0p = &Qs[(8 * dt + t) * QW + 32 * w + g];
            float a[2][4];
#pragma unroll
            for (int mt = 0; mt < 2; mt++) {
                a[mt][0] = q0p[16 * mt];
                a[mt][1] = q0p[16 * mt + 8];
                a[mt][2] = q0p[4 * QW + 16 * mt];
                a[mt][3] = q0p[4 * QW + 16 * mt + 8];
            }
            const float* kb0 = &Ks[(8 * dt + t) * KW + g];
            const float* kb1 = &Ks[(8 * dt + t + 4) * KW + gx];
#pragma unroll
            for (int nt = 0; nt < 8; nt++) {
                float b0 = kb0[8 * nt], b1 = kb1[8 * nt];
                MMA_F(s[0][nt], a[0][0], a[0][1], a[0][2], a[0][3], b0, b1);
                MMA_F(s[1][nt], a[1][0], a[1][1], a[1][2], a[1][3], b0, b1);
            }
        }

        const float* tbp = tb - i * 64;
#pragma unroll
        for (int mt = 0; mt < 2; mt++) {
            const float* tq = tbp + 16 * mt;
            float tm0 = -3.0e38f, tm1 = -3.0e38f;
#pragma unroll
            for (int nt = 0; nt < 8; nt++) {
                int cc = 8 * nt + cb;
                s[mt][nt][0] += tq[g - cc];
                s[mt][nt][1] += tq[g - cc - 1];
                s[mt][nt][2] += tq[g + 8 - cc];
                s[mt][nt][3] += tq[g + 8 - cc - 1];
                tm0 = fmaxf(tm0, fmaxf(s[mt][nt][0], s[mt][nt][1]));
                tm1 = fmaxf(tm1, fmaxf(s[mt][nt][2], s[mt][nt][3]));
            }
            tm0 = fmaxf(tm0, __shfl_xor_sync(0xffffffffu, tm0, 1));
            tm0 = fmaxf(tm0, __shfl_xor_sync(0xffffffffu, tm0, 2));
            tm1 = fmaxf(tm1, __shfl_xor_sync(0xffffffffu, tm1, 1));
            tm1 = fmaxf(tm1, __shfl_xor_sync(0xffffffffu, tm1, 2));
            float mn0 = fmaxf(mx[mt][0], tm0), mn1 = fmaxf(mx[mt][1], tm1);
            bool skip = __all_sync(0xffffffffu,
                                   (mn0 == mx[mt][0]) && (mn1 == mx[mt][1]));
            float rs0 = 0.f, rs1 = 0.f;
#pragma unroll
            for (int nt = 0; nt < 8; nt++) {
                s[mt][nt][0] = __expf(s[mt][nt][0] - mn0);
                s[mt][nt][1] = __expf(s[mt][nt][1] - mn0);
                s[mt][nt][2] = __expf(s[mt][nt][2] - mn1);
                s[mt][nt][3] = __expf(s[mt][nt][3] - mn1);
                rs0 += s[mt][nt][0] + s[mt][nt][1];
                rs1 += s[mt][nt][2] + s[mt][nt][3];
            }
            rs0 += __shfl_xor_sync(0xffffffffu, rs0, 1);
            rs0 += __shfl_xor_sync(0xffffffffu, rs0, 2);
            rs1 += __shfl_xor_sync(0xffffffffu, rs1, 1);
            rs1 += __shfl_xor_sync(0xffffffffu, rs1, 2);
            if (skip) {
                lsum[mt][0] += rs0;
                lsum[mt][1] += rs1;
            } else {
                float sc0 = __expf(mx[mt][0] - mn0);
                float sc1 = __expf(mx[mt][1] - mn1);
                lsum[mt][0] = lsum[mt][0] * sc0 + rs0;
                lsum[mt][1] = lsum[mt][1] * sc1 + rs1;
                mx[mt][0] = mn0; mx[mt][1] = mn1;
#pragma unroll
                for (int nt = 0; nt < 8; nt++) {
                    o[mt][nt][0] *= sc0; o[mt][nt][1] *= sc0;
                    o[mt][nt][2] *= sc1; o[mt][nt][3] *= sc1;
                }
            }
        }

#pragma unroll
        for (int ct = 0; ct < 8; ct++) {
            float pa[2][4];
#pragma unroll
            for (int mt = 0; mt < 2; mt++) {
                float v00 = __shfl_sync(0xffffffffu, s[mt][ct][0], sidx);
                float v01 = __shfl_sync(0xffffffffu, s[mt][ct][1], sidx);
                float v10 = __shfl_sync(0xffffffffu, s[mt][ct][2], sidx);
                float v11 = __shfl_sync(0xffffffffu, s[mt][ct][3], sidx);
                float w00 = __shfl_sync(0xffffffffu, s[mt][ct][0], sidx + 2);
                float w01 = __shfl_sync(0xffffffffu, s[mt][ct][1], sidx + 2);
                float w10 = __shfl_sync(0xffffffffu, s[mt][ct][2], sidx + 2);
                float w11 = __shfl_sync(0xffffffffu, s[mt][ct][3], sidx + 2);
                pa[mt][0] = (t & 1) ? v01 : v00;
                pa[mt][1] = (t & 1) ? v11 : v10;
                pa[mt][2] = (t & 1) ? w01 : w00;
                pa[mt][3] = (t & 1) ? w11 : w10;
            }
            const float* vb = &Vs[g * KW + 8 * ct + t];
#pragma unroll
            for (int nt = 0; nt < 8; nt++) {
                float b0 = vb[8 * nt * KW + sw], b1 = vb[8 * nt * KW + sw4];
                MMA_F(o[0][nt], pa[0][0], pa[0][1], pa[0][2], pa[0][3], b0, b1);
                MMA_F(o[1][nt], pa[1][0], pa[1][1], pa[1][2], pa[1][3], b0, b1);
            }
        }
    }
#undef KV_ISSUE

    size_t hb = (size_t)b * Cc + (size_t)h * CHd;
#pragma unroll
    for (int mt = 0; mt < 2; mt++) {
        float il0 = 1.0f / lsum[mt][0], il1 = 1.0f / lsum[mt][1];
#pragma unroll
        for (int nt = 0; nt < 8; nt++) {
            int d = 8 * nt + cb;
            size_t base = (hb + d) * Tt + q0 + 32 * w + 16 * mt;
            g_a_h[base + g]          = __float2half(o[mt][nt][0] * il0);
            g_a_h[base + Tt + g]     = __float2half(o[mt][nt][1] * il0);
            g_a_h[base + g + 8]      = __float2half(o[mt][nt][2] * il1);
            g_a_h[base + Tt + g + 8] = __float2half(o[mt][nt][3] * il1);
        }
    }
}

// ---------------- launch ----------------
extern "C" void kernel_launch(void* const* d_in, const int* in_sizes, int n_in,
                              void* d_out, int out_size) {
    const float* x       = (const float*)d_in[0];
    const float* gn_w    = (const float*)d_in[1];
    const float* gn_b    = (const float*)d_in[2];
    const float* qkv_w   = (const float*)d_in[3];
    const float* qkv_b   = (const float*)d_in[4];
    const float* proj_w  = (const float*)d_in[5];
    const float* proj_b  = (const float*)d_in[6];
    const float* rel_emb = (const float*)d_in[7];
    float* out = (float*)d_out;
    (void)in_sizes; (void)n_in; (void)out_size;

    __half* wq_h; cudaGetSymbolAddress((void**)&wq_h, g_wq_h);
    __half* wp_h; cudaGetSymbolAddress((void**)&wp_h, g_wp_h);

    cudaFuncSetAttribute(hgemm<false>, cudaFuncAttributeMaxDynamicSharedMemorySize, HGEMM_SMEM);
    cudaFuncSetAttribute(hgemm<true>,  cudaFuncAttributeMaxDynamicSharedMemorySize, HGEMM_SMEM);
    cudaFuncSetAttribute(attn_kernel, cudaFuncAttributeMaxDynamicSharedMemorySize, ATTN_SMEM);

    fill_tab_kernel<<<(Hh * (2 * Tt - 1) + 255) / 256, 256>>>(rel_emb);
    f2h_kernel<<<(3 * Cc * Cc / 8 + 255) / 256, 256>>>(qkv_w, wq_h, 3 * Cc * Cc);
    f2h_kernel<<<(Cc * Cc / 8 + 255) / 256, 256>>>(proj_w, wp_h, Cc * Cc);
    gn1_kernel<<<128, 256>>>(x);
    gn2_kernel<<<256, 256>>>(x, gn_w, gn_b);
    hgemm<false><<<dim3(Tt / 128, (3 * Cc) / 128, Bq), 256, HGEMM_SMEM>>>(wq_h, qkv_b, nullptr, nullptr);
    attn_kernel<<<dim3(Tt / 128, Hh, Bq), 128, ATTN_SMEM>>>();
    hgemm<true><<<dim3(Tt / 128, Cc / 128, Bq), 256, HGEMM_SMEM>>>(wp_h, proj_b, x, out);
}

// round 14
// speedup vs baseline: 1.9807x; 1.4113x over previous
#include <cuda_runtime.h>
#include <cuda_fp16.h>
#include <math.h>
#include <stdint.h>

#define Bq 2
#define Cc 1024
#define Tt 2048
#define Hh 16
#define CHd 64
#define Gg 32

// ---------------- scratch (device globals; no allocations) ----------------
__device__ __half g_xn_h[(size_t)Bq * Cc * Tt];      // GroupNorm output (half)
__device__ __half g_qkv_h[(size_t)Bq * 3 * Cc * Tt]; // QKV output (half)
__device__ __half g_a_h[(size_t)Bq * Cc * Tt];       // attention output (half)
__device__ __half g_wq_h[(size_t)3 * Cc * Cc];
__device__ __half g_wp_h[(size_t)Cc * Cc];
__device__ float  g_tab[Hh * (2 * Tt - 1)];
__device__ float  g_part[128][2];

// ---------------- fp32 -> fp16 weight conversion ----------------
__global__ void f2h_kernel(const float* __restrict__ s, __half* __restrict__ d, int n) {
    int i = (blockIdx.x * 256 + threadIdx.x) * 8;
    if (i >= n) return;
    float4 a = *(const float4*)&s[i];
    float4 b = *(const float4*)&s[i + 4];
    __half2 h[4] = {__floats2half2_rn(a.x, a.y), __floats2half2_rn(a.z, a.w),
                    __floats2half2_rn(b.x, b.y), __floats2half2_rn(b.z, b.w)};
    *(uint4*)&d[i] = *(uint4*)h;
}

// ---------------- relative-position bias table ----------------
__global__ void fill_tab_kernel(const float* __restrict__ rel_emb) {
    int idx = blockIdx.x * 256 + threadIdx.x;
    const int NT = Hh * (2 * Tt - 1);
    if (idx >= NT) return;
    int h = idx / (2 * Tt - 1);
    int di = idx % (2 * Tt - 1);
    int n = di - (Tt - 1);            // n = q - k
    int ret = 0;
    if (n < 0) { ret = 16; n = -n; }
    int bucket;
    if (n < 8) {
        bucket = ret + n;
    } else {
        float v = logf((float)n * 0.125f) / logf(8.0f) * 8.0f;
        int vi = 8 + (int)v;
        if (vi > 15) vi = 15;
        bucket = ret + vi;
    }
    g_tab[h * (2 * Tt - 1) + di] = rel_emb[bucket * Hh + h] * 8.0f;
}

// ---------------- GroupNorm, two-pass ----------------
__global__ __launch_bounds__(256) void gn1_kernel(const float* __restrict__ x) {
    int blk = blockIdx.x;
    int b = blk >> 6, g = (blk >> 1) & 31, half = blk & 1;
    const float* xp = x + ((size_t)b * Cc + (size_t)g * 32) * Tt + half * 32768;
    int tid = threadIdx.x;
    float s = 0.f, s2 = 0.f;
    for (int i = tid * 4; i < 32768; i += 1024) {
        float4 v = *(const float4*)&xp[i];
        s += v.x + v.y + v.z + v.w;
        s2 = fmaf(v.x, v.x, fmaf(v.y, v.y, fmaf(v.z, v.z, fmaf(v.w, v.w, s2))));
    }
    for (int o = 16; o; o >>= 1) {
        s  += __shfl_xor_sync(0xffffffffu, s, o);
        s2 += __shfl_xor_sync(0xffffffffu, s2, o);
    }
    __shared__ float sh[2][8];
    int wid = tid >> 5, ln = tid & 31;
    if (ln == 0) { sh[0][wid] = s; sh[1][wid] = s2; }
    __syncthreads();
    if (tid == 0) {
        float a = 0.f, c = 0.f;
        for (int i = 0; i < 8; i++) { a += sh[0][i]; c += sh[1][i]; }
        g_part[blk][0] = a;
        g_part[blk][1] = c;
    }
}

__global__ __launch_bounds__(256) void gn2_kernel(const float* __restrict__ x,
                                                  const float* __restrict__ w,
                                                  const float* __restrict__ bb) {
    int blk = blockIdx.x;
    int b = blk >> 7, g = (blk >> 2) & 31, q = blk & 3;
    int pi = b * 64 + g * 2;
    float S  = g_part[pi][0] + g_part[pi + 1][0];
    float S2 = g_part[pi][1] + g_part[pi + 1][1];
    float mu = S / 65536.0f;
    float inv = rsqrtf(S2 / 65536.0f - mu * mu + 1e-5f);
    size_t base = ((size_t)b * Cc + (size_t)g * 32) * Tt + q * 16384;
    const float* xp = x + base;
    __half* op = g_xn_h + base;
    int tid = threadIdx.x;
    for (int i = tid * 4; i < 16384; i += 1024) {
        int c = g * 32 + (q * 16384 + i) / 2048;
        float sw = w[c] * inv, sb = bb[c] - mu * sw;
        float4 v = *(const float4*)&xp[i];
        __half2 h0 = __floats2half2_rn(fmaf(v.x, sw, sb), fmaf(v.y, sw, sb));
        __half2 h1 = __floats2half2_rn(fmaf(v.z, sw, sb), fmaf(v.w, sw, sb));
        *(uint2*)&op[i] = make_uint2(*(uint32_t*)&h0, *(uint32_t*)&h1);
    }
}

// ---------------- shared PTX helpers ----------------
#define MMA_H(C, A0, A1, A2, A3, B0, B1) \
    asm volatile("mma.sync.aligned.m16n8k16.row.col.f32.f16.f16.f32 " \
                 "{%0,%1,%2,%3}, {%4,%5,%6,%7}, {%8,%9}, {%0,%1,%2,%3};" \
                 : "+f"((C)[0]), "+f"((C)[1]), "+f"((C)[2]), "+f"((C)[3]) \
                 : "r"(A0), "r"(A1), "r"(A2), "r"(A3), "r"(B0), "r"(B1))

#define LDSM4(R0, R1, R2, R3, ADDR) \
    asm volatile("ldmatrix.sync.aligned.m8n8.x4.shared.b16 {%0,%1,%2,%3}, [%4];" \
                 : "=r"(R0), "=r"(R1), "=r"(R2), "=r"(R3) : "r"(ADDR))

#define LDSM4T(R0, R1, R2, R3, ADDR) \
    asm volatile("ldmatrix.sync.aligned.m8n8.x4.trans.shared.b16 {%0,%1,%2,%3}, [%4];" \
                 : "=r"(R0), "=r"(R1), "=r"(R2), "=r"(R3) : "r"(ADDR))

#define LDSM2T(R0, R1, ADDR) \
    asm volatile("ldmatrix.sync.aligned.m8n8.x2.trans.shared.b16 {%0,%1}, [%2];" \
                 : "=r"(R0), "=r"(R1) : "r"(ADDR))

__device__ __forceinline__ void cp16(uint32_t dst, const void* src) {
    asm volatile("cp.async.cg.shared.global [%0], [%1], 16;" :: "r"(dst), "l"(src));
}
#define CP_COMMIT() asm volatile("cp.async.commit_group;" ::: "memory")
#define CP_WAIT3()  asm volatile("cp.async.wait_group 3;" ::: "memory")
#define CP_WAIT1()  asm volatile("cp.async.wait_group 1;" ::: "memory")

__device__ __forceinline__ uint32_t packh2(float a, float b) {
    __half2 h = __floats2half2_rn(a, b);
    return *(uint32_t*)&h;
}

// ---------------- fp16 GEMM (R13-proven) ----------------
#define HAST 4096
#define HBST 4096
#define HSTG 5
#define HGEMM_SMEM (HSTG * (HAST + HBST))   // 40960 B

template <bool PROJ>
__global__ __launch_bounds__(256, 2) void hgemm(const __half* __restrict__ Wh,
                                                const float* __restrict__ bias,
                                                const float* __restrict__ resid,
                                                float* __restrict__ outp) {
    const int N = Tt, K = Cc;
    int b = blockIdx.z;
    const __half* Xh = (PROJ ? g_a_h : g_xn_h) + (size_t)b * Cc * Tt;
    float* Ob = PROJ ? (outp + (size_t)b * Cc * Tt) : nullptr;
    __half* Obh = PROJ ? nullptr : (g_qkv_h + (size_t)b * 3 * Cc * Tt);
    const float* Rb = PROJ ? (resid + (size_t)b * Cc * Tt) : nullptr;

    extern __shared__ __align__(128) char hs[];
    uint32_t a_u = (uint32_t)__cvta_generic_to_shared(hs);
    uint32_t b_u = a_u + HSTG * HAST;

    int m0 = blockIdx.y * 128, n0 = blockIdx.x * 128;
    int tid = threadIdx.x, lane = tid & 31, warp = tid >> 5;
    int wm = warp & 1, wn = warp >> 1;

    int arow = tid >> 1, ac = tid & 1;
    int brow = tid >> 4, bc = tid & 15;
    const __half* aSrc = Wh + (size_t)(m0 + arow) * K + ac * 8;
    const __half* bSrc = Xh + (size_t)brow * N + n0 + bc * 8;
    uint32_t aDst = a_u + ((arow * 2 + (ac ^ ((arow >> 2) & 1))) << 4);
    uint32_t bDst = b_u + ((brow * 16 + (bc ^ (brow & 7))) << 4);

    int l15 = lane & 15, lc = lane >> 4;
    uint32_t aAddr[4], bAddr[4];
#pragma unroll
    for (int mt = 0; mt < 4; mt++) {
        int row = wm * 64 + mt * 16 + l15;
        aAddr[mt] = a_u + ((row * 2 + (lc ^ ((row >> 2) & 1))) << 4);
    }
#pragma unroll
    for (int nt = 0; nt < 4; nt++) {
        int c = wn * 4 + nt;
        bAddr[nt] = b_u + ((l15 * 16 + (c ^ (l15 & 7))) << 4);
    }

    float acc[4][4][4];
#pragma unroll
    for (int i = 0; i < 4; i++)
#pragma unroll
        for (int j = 0; j < 4; j++)
#pragma unroll
            for (int q = 0; q < 4; q++) acc[i][j][q] = 0.f;

    const int NK = K / 16;

#define HG_ISSUE(ST, KT) do { \
    cp16(aDst + (ST) * HAST, aSrc + (KT)); \
    cp16(bDst + (ST) * HBST, bSrc + (size_t)(KT) * N); \
} while (0)

#pragma unroll
    for (int s = 0; s < 4; s++) {
        HG_ISSUE(s, s * 16);
        CP_COMMIT();
    }

    for (int i = 0; i < NK; i++) {
        int st = i % HSTG;
        CP_WAIT3();
        __syncthreads();
        if (i + 4 < NK) {
            int ns = (i + 4) % HSTG;
            HG_ISSUE(ns, (i + 4) * 16);
        }
        CP_COMMIT();

        uint32_t af[4][4], bf[4][2];
#pragma unroll
        for (int mt = 0; mt < 4; mt++)
            LDSM4(af[mt][0], af[mt][1], af[mt][2], af[mt][3], aAddr[mt] + st * HAST);
#pragma unroll
        for (int nt = 0; nt < 4; nt++)
            LDSM2T(bf[nt][0], bf[nt][1], bAddr[nt] + st * HBST);
#pragma unroll
        for (int mt = 0; mt < 4; mt++)
#pragma unroll
            for (int nt = 0; nt < 4; nt++)
                MMA_H(acc[mt][nt], af[mt][0], af[mt][1], af[mt][2], af[mt][3],
                      bf[nt][0], bf[nt][1]);
    }
#undef HG_ISSUE

    int gid = lane >> 2, tg = lane & 3;
#pragma unroll
    for (int tm = 0; tm < 4; tm++) {
        int rr = m0 + wm * 64 + tm * 16 + gid;
        float b0v = bias[rr], b1v = bias[rr + 8];
#pragma unroll
        for (int tn = 0; tn < 4; tn++) {
            int cc = n0 + wn * 32 + tn * 8 + tg * 2;
            size_t o0 = (size_t)rr * N + cc;
            size_t o1 = (size_t)(rr + 8) * N + cc;
            float2 v0 = make_float2(acc[tm][tn][0] + b0v, acc[tm][tn][1] + b0v);
            float2 v1 = make_float2(acc[tm][tn][2] + b1v, acc[tm][tn][3] + b1v);
            if (PROJ) {
                float2 r0 = *(const float2*)&Rb[o0];
                float2 r1 = *(const float2*)&Rb[o1];
                v0.x += r0.x; v0.y += r0.y;
                v1.x += r1.x; v1.y += r1.y;
                *(float2*)&Ob[o0] = v0;
                *(float2*)&Ob[o1] = v1;
            } else {
                *(uint32_t*)&Obh[o0] = packh2(v0.x, v0.y);
                *(uint32_t*)&Obh[o1] = packh2(v1.x, v1.y);
            }
        }
    }
}

// ---------------- fp16 flash attention: Q=128, 4 warps x m=32 ----------------
// Tiles in natural [d][t] half layout, chunk^=(d&7) swizzle.
// Q/K frags via ldmatrix.x4.trans, V via ldmatrix.x4; P->A-frag with zero shuffles.
#define AQ_BYTES (64 * 256)            // Q tile 16KB
#define AKV_BYTES (64 * 128)           // K or V tile 8KB
#define ATTN_SMEM (AQ_BYTES + 4 * AKV_BYTES)   // 49152 B
__global__ __launch_bounds__(128, 2) void attn_kernel() {
    extern __shared__ char smh[];
    uint32_t q_u = (uint32_t)__cvta_generic_to_shared(smh);
    uint32_t kv_u = q_u + AQ_BYTES;    // [stage][{K,V}][64 rows][128B]

    int q0 = blockIdx.x * 128;
    int h = blockIdx.y;
    int b = blockIdx.z;
    int tid = threadIdx.x, L = tid & 31, w = tid >> 5;

    const __half* qh = g_qkv_h + ((size_t)b * 3 * Cc + (size_t)h * 3 * CHd) * Tt;
    const __half* kh = qh + (size_t)CHd * Tt;
    const __half* vh = qh + (size_t)2 * CHd * Tt;

#define KV_ISSUE(ST, K0) do { \
    _Pragma("unroll") \
    for (int ch = 0; ch < 4; ch++) { \
        int cid = ch * 128 + tid; \
        int d = cid >> 3, c = cid & 7; \
        uint32_t off = d * 128 + ((c ^ (d & 7)) << 4); \
        cp16(kv_u + (ST) * 2 * AKV_BYTES + off, kh + (size_t)d * Tt + (K0) + c * 8); \
        cp16(kv_u + ((ST) * 2 + 1) * AKV_BYTES + off, vh + (size_t)d * Tt + (K0) + c * 8); \
    } \
} while (0)

    KV_ISSUE(0, 0);
    CP_COMMIT();
    // Q tile: 64 rows x 16 chunks
#pragma unroll
    for (int ch = 0; ch < 8; ch++) {
        int cid = ch * 128 + tid;
        int d = cid >> 4, c = cid & 15;
        cp16(q_u + d * 256 + ((c ^ (d & 7)) << 4), qh + (size_t)d * Tt + q0 + c * 8);
    }
    CP_COMMIT();

    float o[2][8][4];
    float mx[2][2], lsum[2][2];
#pragma unroll
    for (int mt = 0; mt < 2; mt++) {
        mx[mt][0] = mx[mt][1] = -3.0e38f;
        lsum[mt][0] = lsum[mt][1] = 0.f;
#pragma unroll
        for (int i = 0; i < 8; i++)
#pragma unroll
            for (int j = 0; j < 4; j++) o[mt][i][j] = 0.f;
    }

    int g = L >> 2, t = L & 3;
    int cb = 2 * t;
    // ldmatrix lane-address components
    int l7 = L & 7, lsel3 = (L >> 3) & 1, lsel4 = (L >> 4) & 1;

    const float* tb = g_tab + h * (2 * Tt - 1) + (Tt - 1) + q0 + 32 * w;
    const float ssc = 0.125f;   // scale^2

    const int NI = Tt / 64;
    for (int i = 0; i < NI; i++) {
        int st = i & 1;
        if (i > 0) __syncthreads();
        if (i + 1 < NI) KV_ISSUE(st ^ 1, (i + 1) * 64);
        CP_COMMIT();
        CP_WAIT1();
        __syncthreads();

        uint32_t Kst = kv_u + st * 2 * AKV_BYTES;
        uint32_t Vst = Kst + AKV_BYTES;

        // ---- S = Q K^T  (fp16 m16n8k16) ----
        float s[2][8][4];
#pragma unroll
        for (int mt = 0; mt < 2; mt++)
#pragma unroll
            for (int nt = 0; nt < 8; nt++)
#pragma unroll
                for (int j = 0; j < 4; j++) s[mt][nt][j] = 0.f;
#pragma unroll
        for (int kc = 0; kc < 4; kc++) {
            uint32_t qa[2][4];
#pragma unroll
            for (int mt = 0; mt < 2; mt++) {
                int dd = 16 * kc + l7 + lsel4 * 8;
                int rc = 4 * w + 2 * mt + lsel3;
                LDSM4T(qa[mt][0], qa[mt][1], qa[mt][2], qa[mt][3],
                       q_u + dd * 256 + ((rc ^ (dd & 7)) << 4));
            }
#pragma unroll
            for (int ntp = 0; ntp < 4; ntp++) {
                uint32_t kb[4];
                int dd = 16 * kc + l7 + lsel3 * 8;
                int ck = 2 * ntp + lsel4;
                LDSM4T(kb[0], kb[1], kb[2], kb[3],
                       Kst + dd * 128 + ((ck ^ (dd & 7)) << 4));
                MMA_H(s[0][2 * ntp],     qa[0][0], qa[0][1], qa[0][2], qa[0][3], kb[0], kb[1]);
                MMA_H(s[1][2 * ntp],     qa[1][0], qa[1][1], qa[1][2], qa[1][3], kb[0], kb[1]);
                MMA_H(s[0][2 * ntp + 1], qa[0][0], qa[0][1], qa[0][2], qa[0][3], kb[2], kb[3]);
                MMA_H(s[1][2 * ntp + 1], qa[1][0], qa[1][1], qa[1][2], qa[1][3], kb[2], kb[3]);
            }
        }

        // ---- scale + bias + online softmax (vote-skip) ----
        const float* tbp = tb - i * 64;
#pragma unroll
        for (int mt = 0; mt < 2; mt++) {
            const float* tq = tbp + 16 * mt;
            float tm0 = -3.0e38f, tm1 = -3.0e38f;
#pragma unroll
            for (int nt = 0; nt < 8; nt++) {
                int cc = 8 * nt + cb;
                s[mt][nt][0] = fmaf(s[mt][nt][0], ssc, tq[g - cc]);
                s[mt][nt][1] = fmaf(s[mt][nt][1], ssc, tq[g - cc - 1]);
                s[mt][nt][2] = fmaf(s[mt][nt][2], ssc, tq[g + 8 - cc]);
                s[mt][nt][3] = fmaf(s[mt][nt][3], ssc, tq[g + 8 - cc - 1]);
                tm0 = fmaxf(tm0, fmaxf(s[mt][nt][0], s[mt][nt][1]));
                tm1 = fmaxf(tm1, fmaxf(s[mt][nt][2], s[mt][nt][3]));
            }
            tm0 = fmaxf(tm0, __shfl_xor_sync(0xffffffffu, tm0, 1));
            tm0 = fmaxf(tm0, __shfl_xor_sync(0xffffffffu, tm0, 2));
            tm1 = fmaxf(tm1, __shfl_xor_sync(0xffffffffu, tm1, 1));
            tm1 = fmaxf(tm1, __shfl_xor_sync(0xffffffffu, tm1, 2));
            float mn0 = fmaxf(mx[mt][0], tm0), mn1 = fmaxf(mx[mt][1], tm1);
            bool skip = __all_sync(0xffffffffu,
                                   (mn0 == mx[mt][0]) && (mn1 == mx[mt][1]));
            float rs0 = 0.f, rs1 = 0.f;
#pragma unroll
            for (int nt = 0; nt < 8; nt++) {
                s[mt][nt][0] = __expf(s[mt][nt][0] - mn0);
                s[mt][nt][1] = __expf(s[mt][nt][1] - mn0);
                s[mt][nt][2] = __expf(s[mt][nt][2] - mn1);
                s[mt][nt][3] = __expf(s[mt][nt][3] - mn1);
                rs0 += s[mt][nt][0] + s[mt][nt][1];
                rs1 += s[mt][nt][2] + s[mt][nt][3];
            }
            rs0 += __shfl_xor_sync(0xffffffffu, rs0, 1);
            rs0 += __shfl_xor_sync(0xffffffffu, rs0, 2);
            rs1 += __shfl_xor_sync(0xffffffffu, rs1, 1);
            rs1 += __shfl_xor_sync(0xffffffffu, rs1, 2);
            if (skip) {
                lsum[mt][0] += rs0;
                lsum[mt][1] += rs1;
            } else {
                float sc0 = __expf(mx[mt][0] - mn0);
                float sc1 = __expf(mx[mt][1] - mn1);
                lsum[mt][0] = lsum[mt][0] * sc0 + rs0;
                lsum[mt][1] = lsum[mt][1] * sc1 + rs1;
                mx[mt][0] = mn0; mx[mt][1] = mn1;
#pragma unroll
                for (int nt = 0; nt < 8; nt++) {
                    o[mt][nt][0] *= sc0; o[mt][nt][1] *= sc0;
                    o[mt][nt][2] *= sc1; o[mt][nt][3] *= sc1;
                }
            }
        }

        // ---- O += P V : P A-frags packed directly from C-frags (no shuffles) ----
#pragma unroll
        for (int kc = 0; kc < 4; kc++) {
            uint32_t pa[2][4];
#pragma unroll
            for (int mt = 0; mt < 2; mt++) {
                pa[mt][0] = packh2(s[mt][2 * kc][0],     s[mt][2 * kc][1]);
                pa[mt][1] = packh2(s[mt][2 * kc][2],     s[mt][2 * kc][3]);
                pa[mt][2] = packh2(s[mt][2 * kc + 1][0], s[mt][2 * kc + 1][1]);
                pa[mt][3] = packh2(s[mt][2 * kc + 1][2], s[mt][2 * kc + 1][3]);
            }
#pragma unroll
            for (int ntp = 0; ntp < 4; ntp++) {
                uint32_t vb[4];
                int row = 16 * ntp + l7 + lsel4 * 8;
                int ck = 2 * kc + lsel3;
                LDSM4(vb[0], vb[1], vb[2], vb[3],
                      Vst + row * 128 + ((ck ^ (row & 7)) << 4));
                MMA_H(o[0][2 * ntp],     pa[0][0], pa[0][1], pa[0][2], pa[0][3], vb[0], vb[1]);
                MMA_H(o[1][2 * ntp],     pa[1][0], pa[1][1], pa[1][2], pa[1][3], vb[0], vb[1]);
                MMA_H(o[0][2 * ntp + 1], pa[0][0], pa[0][1], pa[0][2], pa[0][3], vb[2], vb[3]);
                MMA_H(o[1][2 * ntp + 1], pa[1][0], pa[1][1], pa[1][2], pa[1][3], vb[2], vb[3]);
            }
        }
    }
#undef KV_ISSUE

    size_t hb = (size_t)b * Cc + (size_t)h * CHd;
#pragma unroll
    for (int mt = 0; mt < 2; mt++) {
        float il0 = 1.0f / lsum[mt][0], il1 = 1.0f / lsum[mt][1];
#pragma unroll
        for (int nt = 0; nt < 8; nt++) {
            int d = 8 * nt + cb;
            size_t base = (hb + d) * Tt + q0 + 32 * w + 16 * mt;
            g_a_h[base + g]          = __float2half(o[mt][nt][0] * il0);
            g_a_h[base + Tt + g]     = __float2half(o[mt][nt][1] * il0);
            g_a_h[base + g + 8]      = __float2half(o[mt][nt][2] * il1);
            g_a_h[base + Tt + g + 8] = __float2half(o[mt][nt][3] * il1);
        }
    }
}

// ---------------- launch ----------------
extern "C" void kernel_launch(void* const* d_in, const int* in_sizes, int n_in,
                              void* d_out, int out_size) {
    const float* x       = (const float*)d_in[0];
    const float* gn_w    = (const float*)d_in[1];
    const float* gn_b    = (const float*)d_in[2];
    const float* qkv_w   = (const float*)d_in[3];
    const float* qkv_b   = (const float*)d_in[4];
    const float* proj_w  = (const float*)d_in[5];
    const float* proj_b  = (const float*)d_in[6];
    const float* rel_emb = (const float*)d_in[7];
    float* out = (float*)d_out;
    (void)in_sizes; (void)n_in; (void)out_size;

    __half* wq_h; cudaGetSymbolAddress((void**)&wq_h, g_wq_h);
    __half* wp_h; cudaGetSymbolAddress((void**)&wp_h, g_wp_h);

    cudaFuncSetAttribute(hgemm<false>, cudaFuncAttributeMaxDynamicSharedMemorySize, HGEMM_SMEM);
    cudaFuncSetAttribute(hgemm<true>,  cudaFuncAttributeMaxDynamicSharedMemorySize, HGEMM_SMEM);
    cudaFuncSetAttribute(attn_kernel, cudaFuncAttributeMaxDynamicSharedMemorySize, ATTN_SMEM);

    fill_tab_kernel<<<(Hh * (2 * Tt - 1) + 255) / 256, 256>>>(rel_emb);
    f2h_kernel<<<(3 * Cc * Cc / 8 + 255) / 256, 256>>>(qkv_w, wq_h, 3 * Cc * Cc);
    f2h_kernel<<<(Cc * Cc / 8 + 255) / 256, 256>>>(proj_w, wp_h, Cc * Cc);
    gn1_kernel<<<128, 256>>>(x);
    gn2_kernel<<<256, 256>>>(x, gn_w, gn_b);
    hgemm<false><<<dim3(Tt / 128, (3 * Cc) / 128, Bq), 256, HGEMM_SMEM>>>(wq_h, qkv_b, nullptr, nullptr);
    attn_kernel<<<dim3(Tt / 128, Hh, Bq), 128, ATTN_SMEM>>>();
    hgemm<true><<<dim3(Tt / 128, Cc / 128, Bq), 256, HGEMM_SMEM>>>(wp_h, proj_b, x, out);
}